// round 5
// baseline (speedup 1.0000x reference)
#include <cuda_runtime.h>
#include <cuda_bf16.h>
#include <math.h>
#include <stdint.h>

#define B_ 4
#define N_ 1024
#define HW_ 4096
#define D_ 512
#define H_ 8
#define DK_ 64
#define ZTOT (B_ * H_)
#define ROWS_TOT (ZTOT * N_)

// ---------------- scratch (static device globals; no allocation) -----------
__device__ __nv_bfloat16 g_qh[B_ * N_ * D_],  g_ql[B_ * N_ * D_];
__device__ __nv_bfloat16 g_kh[B_ * HW_ * D_], g_kl[B_ * HW_ * D_];
__device__ __nv_bfloat16 g_vh[B_ * HW_ * D_], g_vl[B_ * HW_ * D_];
__device__ __nv_bfloat16 g_wqh[D_ * D_], g_wql[D_ * D_];
__device__ __nv_bfloat16 g_wkh[D_ * D_], g_wkl[D_ * D_];
__device__ __nv_bfloat16 g_wvh[D_ * D_], g_wvl[D_ * D_];
__device__ __nv_bfloat16 g_woh[D_ * D_], g_wol[D_ * D_];
__device__ __nv_bfloat16 g_Qh[B_ * N_ * D_],  g_Ql[B_ * N_ * D_];
__device__ __nv_bfloat16 g_Kh[B_ * HW_ * D_], g_Kl[B_ * HW_ * D_];
__device__ __nv_bfloat16 g_Vh[B_ * HW_ * D_], g_Vl[B_ * HW_ * D_];
__device__ __nv_bfloat16 g_ctxh[B_ * N_ * D_], g_ctxl[B_ * N_ * D_];
__device__ unsigned char g_mask[N_ * HW_];

// ---------------- helpers --------------------------------------------------
__device__ __forceinline__ uint32_t smem_u32(const void* p) {
    return (uint32_t)__cvta_generic_to_shared(p);
}
__device__ __forceinline__ void cp16(uint32_t s, const void* g) {
    asm volatile("cp.async.cg.shared.global [%0],[%1],16;" :: "r"(s), "l"(g));
}
__device__ __forceinline__ void cp_commit() {
    asm volatile("cp.async.commit_group;" ::: "memory");
}
template <int NN>
__device__ __forceinline__ void cp_wait() {
    asm volatile("cp.async.wait_group %0;" :: "n"(NN) : "memory");
}
__device__ __forceinline__ void ldsm4(uint32_t& r0, uint32_t& r1, uint32_t& r2,
                                      uint32_t& r3, uint32_t a) {
    asm volatile("ldmatrix.sync.aligned.m8n8.x4.shared.b16 {%0,%1,%2,%3},[%4];"
                 : "=r"(r0), "=r"(r1), "=r"(r2), "=r"(r3) : "r"(a));
}
__device__ __forceinline__ void ldsm4t(uint32_t& r0, uint32_t& r1, uint32_t& r2,
                                       uint32_t& r3, uint32_t a) {
    asm volatile("ldmatrix.sync.aligned.m8n8.x4.trans.shared.b16 {%0,%1,%2,%3},[%4];"
                 : "=r"(r0), "=r"(r1), "=r"(r2), "=r"(r3) : "r"(a));
}
__device__ __forceinline__ void mma_bf16(float* c, const uint32_t* a, const uint32_t* b) {
    asm volatile(
        "mma.sync.aligned.m16n8k16.row.col.f32.bf16.bf16.f32 "
        "{%0,%1,%2,%3},{%4,%5,%6,%7},{%8,%9},{%0,%1,%2,%3};"
        : "+f"(c[0]), "+f"(c[1]), "+f"(c[2]), "+f"(c[3])
        : "r"(a[0]), "r"(a[1]), "r"(a[2]), "r"(a[3]), "r"(b[0]), "r"(b[1]));
}
__device__ __forceinline__ void split2(float x, float y, uint32_t& hi, uint32_t& lo) {
    __nv_bfloat16 hx = __float2bfloat16(x);
    __nv_bfloat16 hy = __float2bfloat16(y);
    __nv_bfloat16 lx = __float2bfloat16(x - __bfloat162float(hx));
    __nv_bfloat16 ly = __float2bfloat16(y - __bfloat162float(hy));
    hi = (uint32_t)__bfloat16_as_ushort(hx) | ((uint32_t)__bfloat16_as_ushort(hy) << 16);
    lo = (uint32_t)__bfloat16_as_ushort(lx) | ((uint32_t)__bfloat16_as_ushort(ly) << 16);
}

// ---------------- split fp32 -> hi/lo bf16 ---------------------------------
__global__ void split_kernel(const float4* __restrict__ X, uint2* __restrict__ Xh,
                             uint2* __restrict__ Xl, int n4) {
    int i = blockIdx.x * blockDim.x + threadIdx.x;
    if (i >= n4) return;
    float4 v = X[i];
    uint32_t h0, l0, h1, l1;
    split2(v.x, v.y, h0, l0);
    split2(v.z, v.w, h1, l1);
    Xh[i] = make_uint2(h0, h1);
    Xl[i] = make_uint2(l0, l1);
}

// ---------------- mask precompute ------------------------------------------
__global__ void mask_kernel(const float* __restrict__ x_tilde,
                            const float* __restrict__ x_hat,
                            unsigned char* __restrict__ mask) {
    int idx = blockIdx.x * blockDim.x + threadIdx.x;
    if (idx >= N_ * HW_) return;
    int m = idx & (HW_ - 1);
    float dx = x_tilde[m * 2 + 0] - x_hat[(size_t)idx * 2 + 0];
    float dy = x_tilde[m * 2 + 1] - x_hat[(size_t)idx * 2 + 1];
    mask[idx] = (sqrtf(dx * dx + dy * dy) < 0.1f) ? 1 : 0;
}

// ---------------- pipelined split-bf16 MMA GEMM (C = alpha*A@B^T + bias) ---
// A [M,K] row-major, B [N,K] row-major; both pre-split hi/lo bf16.
template <int BM, int BN, int BK, int WM, int WN, bool SPLITOUT>
__global__ void __launch_bounds__(256) gemm_bf16(
    const __nv_bfloat16* __restrict__ Agh, const __nv_bfloat16* __restrict__ Agl,
    const __nv_bfloat16* __restrict__ Bgh, const __nv_bfloat16* __restrict__ Bgl,
    const float* __restrict__ bias, float* __restrict__ C,
    __nv_bfloat16* __restrict__ Ch, __nv_bfloat16* __restrict__ Cl,
    int K, int lda, int ldb, int ldc,
    long sAb, long sAh0, long sBb, long sBh0, long sCb, long sCh0, float alpha) {
    constexpr int STAGES = 3;
    constexpr int SA = BK + 8;
    constexpr int SB = BK + 8;
    constexpr int ASZ = BM * SA;
    constexpr int BSZ = BN * SB;
    constexpr int STRIDE = 2 * ASZ + 2 * BSZ;
    extern __shared__ __nv_bfloat16 smem[];

    int z = blockIdx.z;
    int zb = z >> 3, zh = z & 7;
    Agh += zb * sAb + zh * sAh0;
    Agl += zb * sAb + zh * sAh0;
    Bgh += zb * sBb + zh * sBh0;
    Bgl += zb * sBb + zh * sBh0;
    long coff = zb * sCb + zh * sCh0;

    int m0 = blockIdx.y * BM;
    int n0 = blockIdx.x * BN;
    int tid = threadIdx.x;
    int lane = tid & 31;
    int wid = tid >> 5;
    constexpr int WNC = BN / WN;
    int wm0 = (wid / WNC) * WM;
    int wn0 = (wid % WNC) * WN;
    constexpr int MT = WM / 16;
    constexpr int NT = WN / 8;
    constexpr int NTP = NT / 2;

    int nK = K / BK;
    uint32_t smem_b = smem_u32(smem);

    auto issue = [&](int kc) {
        int s = kc % STAGES;
        int k0 = kc * BK;
        uint32_t base = smem_b + (uint32_t)(s * STRIDE) * 2;
        for (int i = tid; i < BM * (BK / 8); i += 256) {
            int r = i / (BK / 8);
            int c = (i % (BK / 8)) * 8;
            long go = (long)(m0 + r) * lda + k0 + c;
            uint32_t so = (uint32_t)(r * SA + c) * 2;
            cp16(base + so, Agh + go);
            cp16(base + (uint32_t)ASZ * 2 + so, Agl + go);
        }
        uint32_t bb = base + (uint32_t)(2 * ASZ) * 2;
        for (int i = tid; i < BN * (BK / 8); i += 256) {
            int r = i / (BK / 8);
            int c = (i % (BK / 8)) * 8;
            long go = (long)(n0 + r) * ldb + k0 + c;
            uint32_t so = (uint32_t)(r * SB + c) * 2;
            cp16(bb + so, Bgh + go);
            cp16(bb + (uint32_t)BSZ * 2 + so, Bgl + go);
        }
    };

    float acc[MT][NT][4];
#pragma unroll
    for (int i = 0; i < MT; i++)
#pragma unroll
        for (int j = 0; j < NT; j++)
#pragma unroll
            for (int q = 0; q < 4; q++) acc[i][j][q] = 0.0f;

    for (int s = 0; s < STAGES - 1; s++) {
        if (s < nK) issue(s);
        cp_commit();
    }

    for (int kc = 0; kc < nK; kc++) {
        int pf = kc + STAGES - 1;
        if (pf < nK) issue(pf);
        cp_commit();
        cp_wait<STAGES - 1>();
        __syncthreads();

        int s = kc % STAGES;
        const __nv_bfloat16* Ah_s = smem + s * STRIDE;
        const __nv_bfloat16* Al_s = Ah_s + ASZ;
        const __nv_bfloat16* Bh_s = Ah_s + 2 * ASZ;
        const __nv_bfloat16* Bl_s = Bh_s + BSZ;

#pragma unroll
        for (int ks = 0; ks < BK / 16; ks++) {
            uint32_t af[MT][4], al_[MT][4];
#pragma unroll
            for (int mt = 0; mt < MT; mt++) {
                int row = wm0 + mt * 16 + (lane & 15);
                int col = ks * 16 + (lane >> 4) * 8;
                ldsm4(af[mt][0], af[mt][1], af[mt][2], af[mt][3],
                      smem_u32(&Ah_s[row * SA + col]));
                ldsm4(al_[mt][0], al_[mt][1], al_[mt][2], al_[mt][3],
                      smem_u32(&Al_s[row * SA + col]));
            }
            uint32_t bfr[NT][2], blr[NT][2];
#pragma unroll
            for (int ntp = 0; ntp < NTP; ntp++) {
                int g = lane >> 3;
                int noff = (g >> 1) * 8;
                int koff = (g & 1) * 8;
                uint32_t r0, r1, r2, r3;
                int row = wn0 + ntp * 16 + noff + (lane & 7);
                int col = ks * 16 + koff;
                ldsm4(r0, r1, r2, r3, smem_u32(&Bh_s[row * SB + col]));
                bfr[2 * ntp][0] = r0; bfr[2 * ntp][1] = r1;
                bfr[2 * ntp + 1][0] = r2; bfr[2 * ntp + 1][1] = r3;
                ldsm4(r0, r1, r2, r3, smem_u32(&Bl_s[row * SB + col]));
                blr[2 * ntp][0] = r0; blr[2 * ntp][1] = r1;
                blr[2 * ntp + 1][0] = r2; blr[2 * ntp + 1][1] = r3;
            }
#pragma unroll
            for (int mt = 0; mt < MT; mt++)
#pragma unroll
                for (int nt = 0; nt < NT; nt++) {
                    mma_bf16(acc[mt][nt], af[mt], bfr[nt]);
                    mma_bf16(acc[mt][nt], af[mt], blr[nt]);
                    mma_bf16(acc[mt][nt], al_[mt], bfr[nt]);
                }
        }
        __syncthreads();
    }

    // ---- epilogue ----
#pragma unroll
    for (int mt = 0; mt < MT; mt++)
#pragma unroll
        for (int nt = 0; nt < NT; nt++) {
            int row = m0 + wm0 + mt * 16 + (lane >> 2);
            int col = n0 + wn0 + nt * 8 + (lane & 3) * 2;
            float bx = 0.f, by = 0.f;
            if (bias) { bx = bias[col]; by = bias[col + 1]; }
            float v0x = acc[mt][nt][0] * alpha + bx;
            float v0y = acc[mt][nt][1] * alpha + by;
            float v1x = acc[mt][nt][2] * alpha + bx;
            float v1y = acc[mt][nt][3] * alpha + by;
            if constexpr (SPLITOUT) {
                uint32_t hh, ll;
                split2(v0x, v0y, hh, ll);
                *(uint32_t*)&Ch[coff + (long)row * ldc + col] = hh;
                *(uint32_t*)&Cl[coff + (long)row * ldc + col] = ll;
                split2(v1x, v1y, hh, ll);
                *(uint32_t*)&Ch[coff + (long)(row + 8) * ldc + col] = hh;
                *(uint32_t*)&Cl[coff + (long)(row + 8) * ldc + col] = ll;
            } else {
                *(float2*)&C[coff + (long)row * ldc + col] = make_float2(v0x, v0y);
                *(float2*)&C[coff + (long)(row + 8) * ldc + col] = make_float2(v1x, v1y);
            }
        }
}

// ---------------- masked softmax (max-free, single pass over S) ------------
// scores are O(10): exp(s) is safely inside fp32 range, so no max subtraction.
__global__ __launch_bounds__(256) void softmax_kernel(float* __restrict__ attn,
                                                      const unsigned char* __restrict__ mask) {
    __shared__ float s[HW_];
    __shared__ float red[8];
    __shared__ float bcast;
    long r = blockIdx.x;
    int n = (int)(r % N_);
    float* row = attn + r * (long)HW_;
    const unsigned char* mrow = mask + (long)n * HW_;
    int tid = threadIdx.x;
    int lane = tid & 31;
    int wid = tid >> 5;

    float sum = 0.0f;
    for (int i = tid * 4; i < HW_; i += 1024) {
        float4 v = *(const float4*)(row + i);
        uchar4 mk = *(const uchar4*)(mrow + i);
        v.x = mk.x ? __expf(v.x) : 0.0f;
        v.y = mk.y ? __expf(v.y) : 0.0f;
        v.z = mk.z ? __expf(v.z) : 0.0f;
        v.w = mk.w ? __expf(v.w) : 0.0f;
        *(float4*)(s + i) = v;
        sum += v.x + v.y + v.z + v.w;
    }
#pragma unroll
    for (int o = 16; o; o >>= 1) sum += __shfl_xor_sync(0xffffffffu, sum, o);
    if (lane == 0) red[wid] = sum;
    __syncthreads();
    if (tid == 0) {
        float m = 0.f;
#pragma unroll
        for (int i = 0; i < 8; i++) m += red[i];
        bcast = 1.0f / m;
    }
    __syncthreads();
    float inv = bcast;
    for (int i = tid * 4; i < HW_; i += 1024) {
        float4 v = *(float4*)(s + i);
        v.x *= inv; v.y *= inv; v.z *= inv; v.w *= inv;
        *(float4*)(row + i) = v;
    }
}

// ---------------- ctx = attn(fp32) @ V: convert-on-stage split GEMM --------
// A = attn [rows, HW] fp32 (read + split to bf16 hi/lo during staging)
// B = V [HW, DK] given split (Vh/Vl), output ctx split bf16.
#define PV_BM 128
#define PV_BN 64
#define PV_BK 32
#define PV_SA (PV_BK + 8)
#define PV_SB (PV_BN + 8)
__global__ void __launch_bounds__(256) gemm_pv(
    const float* __restrict__ attn,
    const __nv_bfloat16* __restrict__ Vh, const __nv_bfloat16* __restrict__ Vl,
    __nv_bfloat16* __restrict__ Ch, __nv_bfloat16* __restrict__ Cl) {
    __shared__ __align__(16) __nv_bfloat16 Ah[PV_BM * PV_SA];
    __shared__ __align__(16) __nv_bfloat16 Al[PV_BM * PV_SA];
    __shared__ __align__(16) __nv_bfloat16 Bh[PV_BK * PV_SB];
    __shared__ __align__(16) __nv_bfloat16 Bl[PV_BK * PV_SB];

    int z = blockIdx.y;
    int b = z >> 3, h = z & 7;
    int n0 = blockIdx.x * PV_BM;
    int tid = threadIdx.x;
    int lane = tid & 31;
    int wid = tid >> 5;
    int wm0 = (wid >> 1) * 32;   // 4 m-groups of 32
    int wn0 = (wid & 1) * 32;    // 2 n-groups of 32

    const float* A = attn + ((long)z * N_ + n0) * HW_;
    const __nv_bfloat16* Vbh = Vh + (long)b * HW_ * D_ + h * DK_;
    const __nv_bfloat16* Vbl = Vl + (long)b * HW_ * D_ + h * DK_;

    // prefetch registers
    float4 pa[4];
    uint4 pbh, pbl;
    int ar = tid >> 3;            // 0..31 base row (stride 32 over 128)
    int ac = (tid & 7) * 4;       // float col
    int br = tid >> 3;            // 0..31 (V row within chunk)
    int bc = (tid & 7) * 8;       // bf16 col

    auto prefetch = [&](int kc) {
        int k0 = kc * PV_BK;
#pragma unroll
        for (int t = 0; t < 4; t++)
            pa[t] = *(const float4*)(A + (long)(ar + t * 32) * HW_ + k0 + ac);
        pbh = *(const uint4*)(Vbh + (long)(k0 + br) * D_ + bc);
        pbl = *(const uint4*)(Vbl + (long)(k0 + br) * D_ + bc);
    };

    float acc[2][4][4];
#pragma unroll
    for (int i = 0; i < 2; i++)
#pragma unroll
        for (int j = 0; j < 4; j++)
#pragma unroll
            for (int q = 0; q < 4; q++) acc[i][j][q] = 0.0f;

    prefetch(0);
    const int nK = HW_ / PV_BK;
    for (int kc = 0; kc < nK; kc++) {
        __syncthreads();
        // store prefetched regs to smem (A converted to split bf16)
#pragma unroll
        for (int t = 0; t < 4; t++) {
            uint32_t h0, l0, h1, l1;
            split2(pa[t].x, pa[t].y, h0, l0);
            split2(pa[t].z, pa[t].w, h1, l1);
            int r = ar + t * 32;
            *(uint2*)&Ah[r * PV_SA + ac] = make_uint2(h0, h1);
            *(uint2*)&Al[r * PV_SA + ac] = make_uint2(l0, l1);
        }
        *(uint4*)&Bh[br * PV_SB + bc] = pbh;
        *(uint4*)&Bl[br * PV_SB + bc] = pbl;
        __syncthreads();
        if (kc + 1 < nK) prefetch(kc + 1);

#pragma unroll
        for (int ks = 0; ks < 2; ks++) {
            uint32_t af[2][4], al_[2][4];
#pragma unroll
            for (int mt = 0; mt < 2; mt++) {
                int row = wm0 + mt * 16 + (lane & 15);
                int col = ks * 16 + (lane >> 4) * 8;
                ldsm4(af[mt][0], af[mt][1], af[mt][2], af[mt][3],
                      smem_u32(&Ah[row * PV_SA + col]));
                ldsm4(al_[mt][0], al_[mt][1], al_[mt][2], al_[mt][3],
                      smem_u32(&Al[row * PV_SA + col]));
            }
            uint32_t bh_[4][2], bl_[4][2];
#pragma unroll
            for (int ntp = 0; ntp < 2; ntp++) {
                int g = lane >> 3;
                int noff = (g >> 1) * 8;
                int koff = (g & 1) * 8;
                int row = ks * 16 + koff + (lane & 7);
                int col = wn0 + ntp * 16 + noff;
                uint32_t r0, r1, r2, r3;
                ldsm4t(r0, r1, r2, r3, smem_u32(&Bh[row * PV_SB + col]));
                bh_[2 * ntp][0] = r0; bh_[2 * ntp][1] = r1;
                bh_[2 * ntp + 1][0] = r2; bh_[2 * ntp + 1][1] = r3;
                ldsm4t(r0, r1, r2, r3, smem_u32(&Bl[row * PV_SB + col]));
                bl_[2 * ntp][0] = r0; bl_[2 * ntp][1] = r1;
                bl_[2 * ntp + 1][0] = r2; bl_[2 * ntp + 1][1] = r3;
            }
#pragma unroll
            for (int mt = 0; mt < 2; mt++)
#pragma unroll
                for (int nt = 0; nt < 4; nt++) {
                    mma_bf16(acc[mt][nt], af[mt], bh_[nt]);
                    mma_bf16(acc[mt][nt], af[mt], bl_[nt]);
                    mma_bf16(acc[mt][nt], al_[mt], bh_[nt]);
                }
        }
    }

    // epilogue -> split bf16 ctx
#pragma unroll
    for (int mt = 0; mt < 2; mt++)
#pragma unroll
        for (int nt = 0; nt < 4; nt++) {
            int row = wm0 + mt * 16 + (lane >> 2);
            int col = wn0 + nt * 8 + (lane & 3) * 2;
            long off = ((long)b * N_ + n0 + row) * D_ + h * DK_ + col;
            uint32_t hh, ll;
            split2(acc[mt][nt][0], acc[mt][nt][1], hh, ll);
            *(uint32_t*)&Ch[off] = hh;
            *(uint32_t*)&Cl[off] = ll;
            split2(acc[mt][nt][2], acc[mt][nt][3], hh, ll);
            *(uint32_t*)&Ch[off + 8 * D_] = hh;
            *(uint32_t*)&Cl[off + 8 * D_] = ll;
        }
}

// ---------------- launch ---------------------------------------------------
extern "C" void kernel_launch(void* const* d_in, const int* in_sizes, int n_in,
                              void* d_out, int out_size) {
    const float* query   = (const float*)d_in[0];
    const float* key     = (const float*)d_in[1];
    const float* value   = (const float*)d_in[2];
    const float* x_tilde = (const float*)d_in[3];
    const float* x_hat   = (const float*)d_in[4];
    const float* Wq = (const float*)d_in[5];
    const float* bq = (const float*)d_in[6];
    const float* Wk = (const float*)d_in[7];
    const float* bk = (const float*)d_in[8];
    const float* Wv = (const float*)d_in[9];
    const float* bv = (const float*)d_in[10];
    const float* Wo = (const float*)d_in[11];
    const float* bo = (const float*)d_in[12];

    float* out = (float*)d_out;
    float* attn = out + (size_t)B_ * N_ * D_;

    __nv_bfloat16 *qh, *ql, *kh, *kl, *vh, *vl;
    __nv_bfloat16 *wqh, *wql, *wkh, *wkl, *wvh, *wvl, *woh, *wol;
    __nv_bfloat16 *Qh, *Ql, *Kh, *Kl, *Vh, *Vl, *ch, *cl;
    unsigned char* Mp;
    cudaGetSymbolAddress((void**)&qh, g_qh);   cudaGetSymbolAddress((void**)&ql, g_ql);
    cudaGetSymbolAddress((void**)&kh, g_kh);   cudaGetSymbolAddress((void**)&kl, g_kl);
    cudaGetSymbolAddress((void**)&vh, g_vh);   cudaGetSymbolAddress((void**)&vl, g_vl);
    cudaGetSymbolAddress((void**)&wqh, g_wqh); cudaGetSymbolAddress((void**)&wql, g_wql);
    cudaGetSymbolAddress((void**)&wkh, g_wkh); cudaGetSymbolAddress((void**)&wkl, g_wkl);
    cudaGetSymbolAddress((void**)&wvh, g_wvh); cudaGetSymbolAddress((void**)&wvl, g_wvl);
    cudaGetSymbolAddress((void**)&woh, g_woh); cudaGetSymbolAddress((void**)&wol, g_wol);
    cudaGetSymbolAddress((void**)&Qh, g_Qh);   cudaGetSymbolAddress((void**)&Ql, g_Ql);
    cudaGetSymbolAddress((void**)&Kh, g_Kh);   cudaGetSymbolAddress((void**)&Kl, g_Kl);
    cudaGetSymbolAddress((void**)&Vh, g_Vh);   cudaGetSymbolAddress((void**)&Vl, g_Vl);
    cudaGetSymbolAddress((void**)&ch, g_ctxh); cudaGetSymbolAddress((void**)&cl, g_ctxl);
    cudaGetSymbolAddress((void**)&Mp, g_mask);

    mask_kernel<<<(N_ * HW_ + 255) / 256, 256>>>(x_tilde, x_hat, Mp);

    split_kernel<<<(B_ * N_ * D_ / 4 + 255) / 256, 256>>>(
        (const float4*)query, (uint2*)qh, (uint2*)ql, B_ * N_ * D_ / 4);
    split_kernel<<<(B_ * HW_ * D_ / 4 + 255) / 256, 256>>>(
        (const float4*)key, (uint2*)kh, (uint2*)kl, B_ * HW_ * D_ / 4);
    split_kernel<<<(B_ * HW_ * D_ / 4 + 255) / 256, 256>>>(
        (const float4*)value, (uint2*)vh, (uint2*)vl, B_ * HW_ * D_ / 4);
    split_kernel<<<(D_ * D_ / 4 + 255) / 256, 256>>>(
        (const float4*)Wq, (uint2*)wqh, (uint2*)wql, D_ * D_ / 4);
    split_kernel<<<(D_ * D_ / 4 + 255) / 256, 256>>>(
        (const float4*)Wk, (uint2*)wkh, (uint2*)wkl, D_ * D_ / 4);
    split_kernel<<<(D_ * D_ / 4 + 255) / 256, 256>>>(
        (const float4*)Wv, (uint2*)wvh, (uint2*)wvl, D_ * D_ / 4);
    split_kernel<<<(D_ * D_ / 4 + 255) / 256, 256>>>(
        (const float4*)Wo, (uint2*)woh, (uint2*)wol, D_ * D_ / 4);

    constexpr int SMEM_BIG = 3 * (2 * 128 * 40 + 2 * 128 * 40) * 2;  // 122880

    auto* kProj = gemm_bf16<128, 128, 32, 64, 32, true>;
    auto* kF32  = gemm_bf16<128, 128, 32, 64, 32, false>;
    cudaFuncSetAttribute(kProj, cudaFuncAttributeMaxDynamicSharedMemorySize, SMEM_BIG);
    cudaFuncSetAttribute(kF32, cudaFuncAttributeMaxDynamicSharedMemorySize, SMEM_BIG);

    // projections -> split bf16
    kProj<<<dim3(4, 32, 1), 256, SMEM_BIG>>>(qh, ql, wqh, wql, bq, nullptr, Qh, Ql,
                                             D_, D_, D_, D_, 0, 0, 0, 0, 0, 0, 1.0f);
    kProj<<<dim3(4, 128, 1), 256, SMEM_BIG>>>(kh, kl, wkh, wkl, bk, nullptr, Kh, Kl,
                                              D_, D_, D_, D_, 0, 0, 0, 0, 0, 0, 1.0f);
    kProj<<<dim3(4, 128, 1), 256, SMEM_BIG>>>(vh, vl, wvh, wvl, bv, nullptr, Vh, Vl,
                                              D_, D_, D_, D_, 0, 0, 0, 0, 0, 0, 1.0f);

    // scores: raw S (scaled) into attn buffer
    kF32<<<dim3(32, 8, 32), 256, SMEM_BIG>>>(
        Qh, Ql, Kh, Kl, nullptr, attn, nullptr, nullptr,
        DK_, D_, D_, HW_,
        (long)N_ * D_, DK_, (long)HW_ * D_, DK_,
        (long)H_ * N_ * HW_, (long)N_ * HW_, 0.125f);

    // masked max-free softmax in place -> attn
    softmax_kernel<<<B_ * H_ * N_, 256>>>(attn, Mp);

    // ctx = attn @ V (convert-on-stage), split bf16 out
    gemm_pv<<<dim3(N_ / PV_BM, ZTOT), 256>>>(attn, Vh, Vl, ch, cl);

    // out projection -> fp32
    kF32<<<dim3(4, 32, 1), 256, SMEM_BIG>>>(
        ch, cl, woh, wol, bo, out, nullptr, nullptr,
        D_, D_, D_, D_, 0, 0, 0, 0, 0, 0, 1.0f);
}

// round 7
// speedup vs baseline: 1.4344x; 1.4344x over previous
#include <cuda_runtime.h>
#include <cuda_bf16.h>
#include <math.h>
#include <stdint.h>

#define B_ 4
#define N_ 1024
#define HW_ 4096
#define D_ 512
#define H_ 8
#define DK_ 64
#define ZTOT (B_ * H_)

// ---------------- scratch (static device globals; no allocation) -----------
__device__ __nv_bfloat16 g_qh[B_ * N_ * D_],  g_ql[B_ * N_ * D_];
__device__ __nv_bfloat16 g_kh[B_ * HW_ * D_], g_kl[B_ * HW_ * D_];
__device__ __nv_bfloat16 g_vh[B_ * HW_ * D_], g_vl[B_ * HW_ * D_];
__device__ __nv_bfloat16 g_wqh[D_ * D_], g_wql[D_ * D_];
__device__ __nv_bfloat16 g_wkh[D_ * D_], g_wkl[D_ * D_];
__device__ __nv_bfloat16 g_wvh[D_ * D_], g_wvl[D_ * D_];
__device__ __nv_bfloat16 g_woh[D_ * D_], g_wol[D_ * D_];
__device__ __nv_bfloat16 g_Qh[B_ * N_ * D_],  g_Ql[B_ * N_ * D_];
__device__ __nv_bfloat16 g_Kh[B_ * HW_ * D_], g_Kl[B_ * HW_ * D_];
__device__ __nv_bfloat16 g_Vh[B_ * HW_ * D_], g_Vl[B_ * HW_ * D_];
__device__ __nv_bfloat16 g_ctxh[B_ * N_ * D_], g_ctxl[B_ * N_ * D_];
__device__ unsigned char g_mask[N_ * HW_];

// ---------------- helpers --------------------------------------------------
__device__ __forceinline__ uint32_t smem_u32(const void* p) {
    return (uint32_t)__cvta_generic_to_shared(p);
}
__device__ __forceinline__ void cp16(uint32_t s, const void* g) {
    asm volatile("cp.async.cg.shared.global [%0],[%1],16;" :: "r"(s), "l"(g));
}
__device__ __forceinline__ void cp_commit() {
    asm volatile("cp.async.commit_group;" ::: "memory");
}
template <int NN>
__device__ __forceinline__ void cp_wait() {
    asm volatile("cp.async.wait_group %0;" :: "n"(NN) : "memory");
}
__device__ __forceinline__ void ldsm4(uint32_t& r0, uint32_t& r1, uint32_t& r2,
                                      uint32_t& r3, uint32_t a) {
    asm volatile("ldmatrix.sync.aligned.m8n8.x4.shared.b16 {%0,%1,%2,%3},[%4];"
                 : "=r"(r0), "=r"(r1), "=r"(r2), "=r"(r3) : "r"(a));
}
__device__ __forceinline__ void ldsm4t(uint32_t& r0, uint32_t& r1, uint32_t& r2,
                                       uint32_t& r3, uint32_t a) {
    asm volatile("ldmatrix.sync.aligned.m8n8.x4.trans.shared.b16 {%0,%1,%2,%3},[%4];"
                 : "=r"(r0), "=r"(r1), "=r"(r2), "=r"(r3) : "r"(a));
}
__device__ __forceinline__ void mma_bf16(float* c, const uint32_t* a, const uint32_t* b) {
    asm volatile(
        "mma.sync.aligned.m16n8k16.row.col.f32.bf16.bf16.f32 "
        "{%0,%1,%2,%3},{%4,%5,%6,%7},{%8,%9},{%0,%1,%2,%3};"
        : "+f"(c[0]), "+f"(c[1]), "+f"(c[2]), "+f"(c[3])
        : "r"(a[0]), "r"(a[1]), "r"(a[2]), "r"(a[3]), "r"(b[0]), "r"(b[1]));
}
__device__ __forceinline__ void mma2(float* c, const uint32_t* a, uint32_t b0, uint32_t b1) {
    uint32_t b[2] = {b0, b1};
    mma_bf16(c, a, b);
}
__device__ __forceinline__ void split2(float x, float y, uint32_t& hi, uint32_t& lo) {
    __nv_bfloat16 hx = __float2bfloat16(x);
    __nv_bfloat16 hy = __float2bfloat16(y);
    __nv_bfloat16 lx = __float2bfloat16(x - __bfloat162float(hx));
    __nv_bfloat16 ly = __float2bfloat16(y - __bfloat162float(hy));
    hi = (uint32_t)__bfloat16_as_ushort(hx) | ((uint32_t)__bfloat16_as_ushort(hy) << 16);
    lo = (uint32_t)__bfloat16_as_ushort(lx) | ((uint32_t)__bfloat16_as_ushort(ly) << 16);
}

// ---------------- split fp32 -> hi/lo bf16 ---------------------------------
__global__ void split_kernel(const float4* __restrict__ X, uint2* __restrict__ Xh,
                             uint2* __restrict__ Xl, int n4) {
    int i = blockIdx.x * blockDim.x + threadIdx.x;
    if (i >= n4) return;
    float4 v = X[i];
    uint32_t h0, l0, h1, l1;
    split2(v.x, v.y, h0, l0);
    split2(v.z, v.w, h1, l1);
    Xh[i] = make_uint2(h0, h1);
    Xl[i] = make_uint2(l0, l1);
}

// ---------------- mask precompute ------------------------------------------
__global__ void mask_kernel(const float* __restrict__ x_tilde,
                            const float* __restrict__ x_hat,
                            unsigned char* __restrict__ mask) {
    int idx = blockIdx.x * blockDim.x + threadIdx.x;
    if (idx >= N_ * HW_) return;
    int m = idx & (HW_ - 1);
    float dx = x_tilde[m * 2 + 0] - x_hat[(size_t)idx * 2 + 0];
    float dy = x_tilde[m * 2 + 1] - x_hat[(size_t)idx * 2 + 1];
    mask[idx] = (sqrtf(dx * dx + dy * dy) < 0.1f) ? 1 : 0;
}

// ---------------- pipelined split-bf16 MMA GEMM (C = A@B^T + bias) ---------
template <int BM, int BN, int BK, int WM, int WN, bool SPLITOUT>
__global__ void __launch_bounds__(256) gemm_bf16(
    const __nv_bfloat16* __restrict__ Agh, const __nv_bfloat16* __restrict__ Agl,
    const __nv_bfloat16* __restrict__ Bgh, const __nv_bfloat16* __restrict__ Bgl,
    const float* __restrict__ bias, float* __restrict__ C,
    __nv_bfloat16* __restrict__ Ch, __nv_bfloat16* __restrict__ Cl,
    int K, int lda, int ldb, int ldc) {
    constexpr int STAGES = 3;
    constexpr int SA = BK + 8;
    constexpr int SB = BK + 8;
    constexpr int ASZ = BM * SA;
    constexpr int BSZ = BN * SB;
    constexpr int STRIDE = 2 * ASZ + 2 * BSZ;
    extern __shared__ __nv_bfloat16 smem[];

    int m0 = blockIdx.y * BM;
    int n0 = blockIdx.x * BN;
    int tid = threadIdx.x;
    int lane = tid & 31;
    int wid = tid >> 5;
    constexpr int WNC = BN / WN;
    int wm0 = (wid / WNC) * WM;
    int wn0 = (wid % WNC) * WN;
    constexpr int MT = WM / 16;
    constexpr int NT = WN / 8;
    constexpr int NTP = NT / 2;

    int nK = K / BK;
    uint32_t smem_b = smem_u32(smem);

    auto issue = [&](int kc) {
        int s = kc % STAGES;
        int k0 = kc * BK;
        uint32_t base = smem_b + (uint32_t)(s * STRIDE) * 2;
        for (int i = tid; i < BM * (BK / 8); i += 256) {
            int r = i / (BK / 8);
            int c = (i % (BK / 8)) * 8;
            long go = (long)(m0 + r) * lda + k0 + c;
            uint32_t so = (uint32_t)(r * SA + c) * 2;
            cp16(base + so, Agh + go);
            cp16(base + (uint32_t)ASZ * 2 + so, Agl + go);
        }
        uint32_t bb = base + (uint32_t)(2 * ASZ) * 2;
        for (int i = tid; i < BN * (BK / 8); i += 256) {
            int r = i / (BK / 8);
            int c = (i % (BK / 8)) * 8;
            long go = (long)(n0 + r) * ldb + k0 + c;
            uint32_t so = (uint32_t)(r * SB + c) * 2;
            cp16(bb + so, Bgh + go);
            cp16(bb + (uint32_t)BSZ * 2 + so, Bgl + go);
        }
    };

    float acc[MT][NT][4];
#pragma unroll
    for (int i = 0; i < MT; i++)
#pragma unroll
        for (int j = 0; j < NT; j++)
#pragma unroll
            for (int q = 0; q < 4; q++) acc[i][j][q] = 0.0f;

    for (int s = 0; s < STAGES - 1; s++) {
        if (s < nK) issue(s);
        cp_commit();
    }

    for (int kc = 0; kc < nK; kc++) {
        int pf = kc + STAGES - 1;
        if (pf < nK) issue(pf);
        cp_commit();
        cp_wait<STAGES - 1>();
        __syncthreads();

        int s = kc % STAGES;
        const __nv_bfloat16* Ah_s = smem + s * STRIDE;
        const __nv_bfloat16* Al_s = Ah_s + ASZ;
        const __nv_bfloat16* Bh_s = Ah_s + 2 * ASZ;
        const __nv_bfloat16* Bl_s = Bh_s + BSZ;

#pragma unroll
        for (int ks = 0; ks < BK / 16; ks++) {
            uint32_t af[MT][4], al_[MT][4];
#pragma unroll
            for (int mt = 0; mt < MT; mt++) {
                int row = wm0 + mt * 16 + (lane & 15);
                int col = ks * 16 + (lane >> 4) * 8;
                ldsm4(af[mt][0], af[mt][1], af[mt][2], af[mt][3],
                      smem_u32(&Ah_s[row * SA + col]));
                ldsm4(al_[mt][0], al_[mt][1], al_[mt][2], al_[mt][3],
                      smem_u32(&Al_s[row * SA + col]));
            }
            uint32_t bfr[NT][2], blr[NT][2];
#pragma unroll
            for (int ntp = 0; ntp < NTP; ntp++) {
                int g = lane >> 3;
                int noff = (g >> 1) * 8;
                int koff = (g & 1) * 8;
                uint32_t r0, r1, r2, r3;
                int row = wn0 + ntp * 16 + noff + (lane & 7);
                int col = ks * 16 + koff;
                ldsm4(r0, r1, r2, r3, smem_u32(&Bh_s[row * SB + col]));
                bfr[2 * ntp][0] = r0; bfr[2 * ntp][1] = r1;
                bfr[2 * ntp + 1][0] = r2; bfr[2 * ntp + 1][1] = r3;
                ldsm4(r0, r1, r2, r3, smem_u32(&Bl_s[row * SB + col]));
                blr[2 * ntp][0] = r0; blr[2 * ntp][1] = r1;
                blr[2 * ntp + 1][0] = r2; blr[2 * ntp + 1][1] = r3;
            }
#pragma unroll
            for (int mt = 0; mt < MT; mt++)
#pragma unroll
                for (int nt = 0; nt < NT; nt++) {
                    mma_bf16(acc[mt][nt], af[mt], bfr[nt]);
                    mma_bf16(acc[mt][nt], af[mt], blr[nt]);
                    mma_bf16(acc[mt][nt], al_[mt], bfr[nt]);
                }
        }
        __syncthreads();
    }

#pragma unroll
    for (int mt = 0; mt < MT; mt++)
#pragma unroll
        for (int nt = 0; nt < NT; nt++) {
            int row = m0 + wm0 + mt * 16 + (lane >> 2);
            int col = n0 + wn0 + nt * 8 + (lane & 3) * 2;
            float bx = 0.f, by = 0.f;
            if (bias) { bx = bias[col]; by = bias[col + 1]; }
            float v0x = acc[mt][nt][0] + bx;
            float v0y = acc[mt][nt][1] + by;
            float v1x = acc[mt][nt][2] + bx;
            float v1y = acc[mt][nt][3] + by;
            if constexpr (SPLITOUT) {
                uint32_t hh, ll;
                split2(v0x, v0y, hh, ll);
                *(uint32_t*)&Ch[(long)row * ldc + col] = hh;
                *(uint32_t*)&Cl[(long)row * ldc + col] = ll;
                split2(v1x, v1y, hh, ll);
                *(uint32_t*)&Ch[(long)(row + 8) * ldc + col] = hh;
                *(uint32_t*)&Cl[(long)(row + 8) * ldc + col] = ll;
            } else {
                *(float2*)&C[(long)row * ldc + col] = make_float2(v0x, v0y);
                *(float2*)&C[(long)(row + 8) * ldc + col] = make_float2(v1x, v1y);
            }
        }
}

// ---------------- fused flash-style attention -------------------------------
// Block = (z, 128 q rows), 256 threads (8 warps, warp w owns rows w*16..+15).
// Pass 1: stream K/V/mask chunks; S=Q@K^T in regs; e=mask?exp(s/8):0;
//         rowsums; ctx += E@V (E converted in-register to A-fragments).
// Pass 2: recompute S, write attn = e * (1/rowsum). Only DRAM: attn write.
#define CH_ 128
#define KROW_ 72          // 64 bf16 + 8 pad
#define KSZB_ (128 * KROW_ * 2)            // 18432 bytes per K/V buffer
#define MROW_ 144                          // mask row bytes
#define MSZB_ (128 * MROW_)                // 18432
#define STAGEB_ (4 * KSZB_ + MSZB_)        // 92160
#define FUSED_SMEM (2 * STAGEB_)           // 184320

__global__ void __launch_bounds__(256) fused_attn(
    const __nv_bfloat16* __restrict__ Qh, const __nv_bfloat16* __restrict__ Ql,
    const __nv_bfloat16* __restrict__ Kh, const __nv_bfloat16* __restrict__ Kl,
    const __nv_bfloat16* __restrict__ Vh, const __nv_bfloat16* __restrict__ Vl,
    const unsigned char* __restrict__ mask, float* __restrict__ attn,
    __nv_bfloat16* __restrict__ Ch, __nv_bfloat16* __restrict__ Cl) {
    extern __shared__ char smc[];
    uint32_t sb = smem_u32(smc);

    int z = blockIdx.y;
    int b = z >> 3, h = z & 7;
    int q0 = blockIdx.x * 128;
    int tid = threadIdx.x;
    int lane = tid & 31;
    int w = tid >> 5;
    int lr = lane >> 2;     // 0..7
    int lq = lane & 3;

    const __nv_bfloat16* Qbh = Qh + ((long)(b * N_ + q0)) * D_ + h * DK_;
    const __nv_bfloat16* Qbl = Ql + ((long)(b * N_ + q0)) * D_ + h * DK_;
    const __nv_bfloat16* Kbh = Kh + (long)b * HW_ * D_ + h * DK_;
    const __nv_bfloat16* Kbl = Kl + (long)b * HW_ * D_ + h * DK_;
    const __nv_bfloat16* Vbh = Vh + (long)b * HW_ * D_ + h * DK_;
    const __nv_bfloat16* Vbl = Vl + (long)b * HW_ * D_ + h * DK_;
    const unsigned char* mrow = mask + (long)q0 * HW_;
    float* attn_z = attn + ((long)z * N_ + q0) * HW_;

    // ---- stage Q into buffer0 K area, load Q fragments into registers ----
    for (int i = tid; i < 1024; i += 256) {
        int r = i >> 3;
        int c = (i & 7) * 8;
        cp16(sb + (uint32_t)(r * KROW_ + c) * 2, Qbh + (long)r * D_ + c);
        cp16(sb + KSZB_ + (uint32_t)(r * KROW_ + c) * 2, Qbl + (long)r * D_ + c);
    }
    cp_commit();
    cp_wait<0>();
    __syncthreads();

    uint32_t qfh[4][4], qfl[4][4];
#pragma unroll
    for (int ks = 0; ks < 4; ks++) {
        int row = w * 16 + (lane & 15);
        int col = ks * 16 + (lane >> 4) * 8;
        ldsm4(qfh[ks][0], qfh[ks][1], qfh[ks][2], qfh[ks][3],
              sb + (uint32_t)(row * KROW_ + col) * 2);
        ldsm4(qfl[ks][0], qfl[ks][1], qfl[ks][2], qfl[ks][3],
              sb + KSZB_ + (uint32_t)(row * KROW_ + col) * 2);
    }
    __syncthreads();

    auto issue_kv = [&](int kc, bool with_v) {
        uint32_t base = sb + (uint32_t)((kc & 1) * STAGEB_);
        int mc = kc * CH_;
        for (int i = tid; i < 1024; i += 256) {
            int r = i >> 3;
            int c = (i & 7) * 8;
            long go = (long)(mc + r) * D_ + c;
            uint32_t so = (uint32_t)(r * KROW_ + c) * 2;
            cp16(base + so, Kbh + go);
            cp16(base + KSZB_ + so, Kbl + go);
            if (with_v) {
                cp16(base + 2 * KSZB_ + so, Vbh + go);
                cp16(base + 3 * KSZB_ + so, Vbl + go);
            }
        }
        for (int i = tid; i < 1024; i += 256) {
            int r = i >> 3;
            int c = (i & 7) * 16;
            cp16(base + 4 * KSZB_ + (uint32_t)(r * MROW_ + c),
                 mrow + (long)r * HW_ + mc + c);
        }
    };

    float ctx[8][4];
#pragma unroll
    for (int j = 0; j < 8; j++)
#pragma unroll
        for (int q = 0; q < 4; q++) ctx[j][q] = 0.0f;
    float rs0 = 0.0f, rs1 = 0.0f;

    float sacc[16][4];

    // ================= PASS 1: rowsums + ctx =================
    issue_kv(0, true);
    cp_commit();
    for (int kc = 0; kc < HW_ / CH_; kc++) {
        if (kc + 1 < HW_ / CH_) {
            issue_kv(kc + 1, true);
            cp_commit();
            cp_wait<1>();
        } else {
            cp_wait<0>();
        }
        __syncthreads();

        uint32_t base = sb + (uint32_t)((kc & 1) * STAGEB_);
        uint32_t kh_b = base, kl_b = base + KSZB_;
        uint32_t vh_b = base + 2 * KSZB_, vl_b = base + 3 * KSZB_;
        uint32_t mk_b = base + 4 * KSZB_;

#pragma unroll
        for (int nt = 0; nt < 16; nt++)
#pragma unroll
            for (int q = 0; q < 4; q++) sacc[nt][q] = 0.0f;

        // S = Q @ K^T
#pragma unroll
        for (int ks = 0; ks < 4; ks++) {
#pragma unroll
            for (int ntp = 0; ntp < 8; ntp++) {
                int g = lane >> 3;
                int row = ntp * 16 + (g >> 1) * 8 + (lane & 7);
                int col = ks * 16 + (g & 1) * 8;
                uint32_t h0, h1, h2, h3, l0, l1, l2, l3;
                ldsm4(h0, h1, h2, h3, kh_b + (uint32_t)(row * KROW_ + col) * 2);
                ldsm4(l0, l1, l2, l3, kl_b + (uint32_t)(row * KROW_ + col) * 2);
                mma2(sacc[2 * ntp], qfh[ks], h0, h1);
                mma2(sacc[2 * ntp], qfh[ks], l0, l1);
                mma2(sacc[2 * ntp], qfl[ks], h0, h1);
                mma2(sacc[2 * ntp + 1], qfh[ks], h2, h3);
                mma2(sacc[2 * ntp + 1], qfh[ks], l2, l3);
                mma2(sacc[2 * ntp + 1], qfl[ks], h2, h3);
            }
        }

        // mask + exp + rowsum (E left in sacc)
#pragma unroll
        for (int nt = 0; nt < 16; nt++) {
            uint32_t mo = (uint32_t)((w * 16 + lr) * MROW_ + nt * 8 + lq * 2);
            unsigned short m0 = *(unsigned short*)(smc + (mk_b - sb) + mo);
            unsigned short m1 = *(unsigned short*)(smc + (mk_b - sb) + mo + 8 * MROW_);
            float e0 = (m0 & 0xFF) ? __expf(sacc[nt][0] * 0.125f) : 0.0f;
            float e1 = (m0 >> 8)   ? __expf(sacc[nt][1] * 0.125f) : 0.0f;
            float e2 = (m1 & 0xFF) ? __expf(sacc[nt][2] * 0.125f) : 0.0f;
            float e3 = (m1 >> 8)   ? __expf(sacc[nt][3] * 0.125f) : 0.0f;
            rs0 += e0 + e1;
            rs1 += e2 + e3;
            sacc[nt][0] = e0; sacc[nt][1] = e1;
            sacc[nt][2] = e2; sacc[nt][3] = e3;
        }

        // ctx += E @ V  (E fragments -> A fragments in-register)
        // n-tiles: DK=64 -> ntp 0..3 (16 cols each)  [R6 bug: was ntp<2]
#pragma unroll
        for (int kt = 0; kt < 8; kt++) {
            uint32_t ah[4], al_[4];
            split2(sacc[2 * kt][0], sacc[2 * kt][1], ah[0], al_[0]);
            split2(sacc[2 * kt][2], sacc[2 * kt][3], ah[1], al_[1]);
            split2(sacc[2 * kt + 1][0], sacc[2 * kt + 1][1], ah[2], al_[2]);
            split2(sacc[2 * kt + 1][2], sacc[2 * kt + 1][3], ah[3], al_[3]);
#pragma unroll
            for (int ntp = 0; ntp < 4; ntp++) {
                int g = lane >> 3;
                int row = kt * 16 + (g & 1) * 8 + (lane & 7);
                int col = ntp * 16 + (g >> 1) * 8;
                uint32_t h0, h1, h2, h3, l0, l1, l2, l3;
                ldsm4t(h0, h1, h2, h3, vh_b + (uint32_t)(row * KROW_ + col) * 2);
                ldsm4t(l0, l1, l2, l3, vl_b + (uint32_t)(row * KROW_ + col) * 2);
                mma2(ctx[2 * ntp], ah, h0, h1);
                mma2(ctx[2 * ntp], ah, l0, l1);
                mma2(ctx[2 * ntp], al_, h0, h1);
                mma2(ctx[2 * ntp + 1], ah, h2, h3);
                mma2(ctx[2 * ntp + 1], ah, l2, l3);
                mma2(ctx[2 * ntp + 1], al_, h2, h3);
            }
        }
        __syncthreads();
    }

    // rowsum reduce across the 4 lanes of each row
    rs0 += __shfl_xor_sync(0xffffffffu, rs0, 1);
    rs0 += __shfl_xor_sync(0xffffffffu, rs0, 2);
    rs1 += __shfl_xor_sync(0xffffffffu, rs1, 1);
    rs1 += __shfl_xor_sync(0xffffffffu, rs1, 2);
    float inv0 = 1.0f / rs0;
    float inv1 = 1.0f / rs1;

    // scale + write ctx (split bf16)
#pragma unroll
    for (int nt = 0; nt < 8; nt++) {
        int row = w * 16 + lr;
        int col = nt * 8 + lq * 2;
        long off = ((long)(b * N_ + q0 + row)) * D_ + h * DK_ + col;
        uint32_t hh, ll;
        split2(ctx[nt][0] * inv0, ctx[nt][1] * inv0, hh, ll);
        *(uint32_t*)&Ch[off] = hh;
        *(uint32_t*)&Cl[off] = ll;
        split2(ctx[nt][2] * inv1, ctx[nt][3] * inv1, hh, ll);
        *(uint32_t*)&Ch[off + 8 * D_] = hh;
        *(uint32_t*)&Cl[off + 8 * D_] = ll;
    }

    // ================= PASS 2: recompute S, write normalized attn ==========
    issue_kv(0, false);
    cp_commit();
    for (int kc = 0; kc < HW_ / CH_; kc++) {
        if (kc + 1 < HW_ / CH_) {
            issue_kv(kc + 1, false);
            cp_commit();
            cp_wait<1>();
        } else {
            cp_wait<0>();
        }
        __syncthreads();

        uint32_t base = sb + (uint32_t)((kc & 1) * STAGEB_);
        uint32_t kh_b = base, kl_b = base + KSZB_;
        uint32_t mk_b = base + 4 * KSZB_;
        int mc = kc * CH_;

#pragma unroll
        for (int nt = 0; nt < 16; nt++)
#pragma unroll
            for (int q = 0; q < 4; q++) sacc[nt][q] = 0.0f;

#pragma unroll
        for (int ks = 0; ks < 4; ks++) {
#pragma unroll
            for (int ntp = 0; ntp < 8; ntp++) {
                int g = lane >> 3;
                int row = ntp * 16 + (g >> 1) * 8 + (lane & 7);
                int col = ks * 16 + (g & 1) * 8;
                uint32_t h0, h1, h2, h3, l0, l1, l2, l3;
                ldsm4(h0, h1, h2, h3, kh_b + (uint32_t)(row * KROW_ + col) * 2);
                ldsm4(l0, l1, l2, l3, kl_b + (uint32_t)(row * KROW_ + col) * 2);
                mma2(sacc[2 * ntp], qfh[ks], h0, h1);
                mma2(sacc[2 * ntp], qfh[ks], l0, l1);
                mma2(sacc[2 * ntp], qfl[ks], h0, h1);
                mma2(sacc[2 * ntp + 1], qfh[ks], h2, h3);
                mma2(sacc[2 * ntp + 1], qfh[ks], l2, l3);
                mma2(sacc[2 * ntp + 1], qfl[ks], h2, h3);
            }
        }

        int grow0 = w * 16 + lr;
#pragma unroll
        for (int nt = 0; nt < 16; nt++) {
            uint32_t mo = (uint32_t)(grow0 * MROW_ + nt * 8 + lq * 2);
            unsigned short m0 = *(unsigned short*)(smc + (mk_b - sb) + mo);
            unsigned short m1 = *(unsigned short*)(smc + (mk_b - sb) + mo + 8 * MROW_);
            float e0 = (m0 & 0xFF) ? __expf(sacc[nt][0] * 0.125f) * inv0 : 0.0f;
            float e1 = (m0 >> 8)   ? __expf(sacc[nt][1] * 0.125f) * inv0 : 0.0f;
            float e2 = (m1 & 0xFF) ? __expf(sacc[nt][2] * 0.125f) * inv1 : 0.0f;
            float e3 = (m1 >> 8)   ? __expf(sacc[nt][3] * 0.125f) * inv1 : 0.0f;
            int col = mc + nt * 8 + lq * 2;
            *(float2*)(attn_z + (long)grow0 * HW_ + col) = make_float2(e0, e1);
            *(float2*)(attn_z + (long)(grow0 + 8) * HW_ + col) = make_float2(e2, e3);
        }
        __syncthreads();
    }
}

// ---------------- launch ---------------------------------------------------
extern "C" void kernel_launch(void* const* d_in, const int* in_sizes, int n_in,
                              void* d_out, int out_size) {
    const float* query   = (const float*)d_in[0];
    const float* key     = (const float*)d_in[1];
    const float* value   = (const float*)d_in[2];
    const float* x_tilde = (const float*)d_in[3];
    const float* x_hat   = (const float*)d_in[4];
    const float* Wq = (const float*)d_in[5];
    const float* bq = (const float*)d_in[6];
    const float* Wk = (const float*)d_in[7];
    const float* bk = (const float*)d_in[8];
    const float* Wv = (const float*)d_in[9];
    const float* bv = (const float*)d_in[10];
    const float* Wo = (const float*)d_in[11];
    const float* bo = (const float*)d_in[12];

    float* out = (float*)d_out;
    float* attn = out + (size_t)B_ * N_ * D_;

    __nv_bfloat16 *qh, *ql, *kh, *kl, *vh, *vl;
    __nv_bfloat16 *wqh, *wql, *wkh, *wkl, *wvh, *wvl, *woh, *wol;
    __nv_bfloat16 *Qh, *Ql, *Kh, *Kl, *Vh, *Vl, *ch, *cl;
    unsigned char* Mp;
    cudaGetSymbolAddress((void**)&qh, g_qh);   cudaGetSymbolAddress((void**)&ql, g_ql);
    cudaGetSymbolAddress((void**)&kh, g_kh);   cudaGetSymbolAddress((void**)&kl, g_kl);
    cudaGetSymbolAddress((void**)&vh, g_vh);   cudaGetSymbolAddress((void**)&vl, g_vl);
    cudaGetSymbolAddress((void**)&wqh, g_wqh); cudaGetSymbolAddress((void**)&wql, g_wql);
    cudaGetSymbolAddress((void**)&wkh, g_wkh); cudaGetSymbolAddress((void**)&wkl, g_wkl);
    cudaGetSymbolAddress((void**)&wvh, g_wvh); cudaGetSymbolAddress((void**)&wvl, g_wvl);
    cudaGetSymbolAddress((void**)&woh, g_woh); cudaGetSymbolAddress((void**)&wol, g_wol);
    cudaGetSymbolAddress((void**)&Qh, g_Qh);   cudaGetSymbolAddress((void**)&Ql, g_Ql);
    cudaGetSymbolAddress((void**)&Kh, g_Kh);   cudaGetSymbolAddress((void**)&Kl, g_Kl);
    cudaGetSymbolAddress((void**)&Vh, g_Vh);   cudaGetSymbolAddress((void**)&Vl, g_Vl);
    cudaGetSymbolAddress((void**)&ch, g_ctxh); cudaGetSymbolAddress((void**)&cl, g_ctxl);
    cudaGetSymbolAddress((void**)&Mp, g_mask);

    mask_kernel<<<(N_ * HW_ + 255) / 256, 256>>>(x_tilde, x_hat, Mp);

    split_kernel<<<(B_ * N_ * D_ / 4 + 255) / 256, 256>>>(
        (const float4*)query, (uint2*)qh, (uint2*)ql, B_ * N_ * D_ / 4);
    split_kernel<<<(B_ * HW_ * D_ / 4 + 255) / 256, 256>>>(
        (const float4*)key, (uint2*)kh, (uint2*)kl, B_ * HW_ * D_ / 4);
    split_kernel<<<(B_ * HW_ * D_ / 4 + 255) / 256, 256>>>(
        (const float4*)value, (uint2*)vh, (uint2*)vl, B_ * HW_ * D_ / 4);
    split_kernel<<<(D_ * D_ / 4 + 255) / 256, 256>>>(
        (const float4*)Wq, (uint2*)wqh, (uint2*)wql, D_ * D_ / 4);
    split_kernel<<<(D_ * D_ / 4 + 255) / 256, 256>>>(
        (const float4*)Wk, (uint2*)wkh, (uint2*)wkl, D_ * D_ / 4);
    split_kernel<<<(D_ * D_ / 4 + 255) / 256, 256>>>(
        (const float4*)Wv, (uint2*)wvh, (uint2*)wvl, D_ * D_ / 4);
    split_kernel<<<(D_ * D_ / 4 + 255) / 256, 256>>>(
        (const float4*)Wo, (uint2*)woh, (uint2*)wol, D_ * D_ / 4);

    constexpr int SMEM_BIG = 3 * (2 * 128 * 40 + 2 * 128 * 40) * 2;  // 122880

    auto* kProj = gemm_bf16<128, 128, 32, 64, 32, true>;
    auto* kF32  = gemm_bf16<128, 128, 32, 64, 32, false>;
    cudaFuncSetAttribute(kProj, cudaFuncAttributeMaxDynamicSharedMemorySize, SMEM_BIG);
    cudaFuncSetAttribute(kF32, cudaFuncAttributeMaxDynamicSharedMemorySize, SMEM_BIG);
    cudaFuncSetAttribute(fused_attn, cudaFuncAttributeMaxDynamicSharedMemorySize,
                         FUSED_SMEM);

    // projections -> split bf16
    kProj<<<dim3(4, 32, 1), 256, SMEM_BIG>>>(qh, ql, wqh, wql, bq, nullptr, Qh, Ql,
                                             D_, D_, D_, D_);
    kProj<<<dim3(4, 128, 1), 256, SMEM_BIG>>>(kh, kl, wkh, wkl, bk, nullptr, Kh, Kl,
                                              D_, D_, D_, D_);
    kProj<<<dim3(4, 128, 1), 256, SMEM_BIG>>>(vh, vl, wvh, wvl, bv, nullptr, Vh, Vl,
                                              D_, D_, D_, D_);

    // fused: scores + softmax + attn write + ctx
    fused_attn<<<dim3(N_ / 128, ZTOT), 256, FUSED_SMEM>>>(
        Qh, Ql, Kh, Kl, Vh, Vl, Mp, attn, ch, cl);

    // out projection -> fp32
    kF32<<<dim3(4, 32, 1), 256, SMEM_BIG>>>(
        ch, cl, woh, wol, bo, out, nullptr, nullptr,
        D_, D_, D_, D_);
}

// round 10
// speedup vs baseline: 1.4866x; 1.0364x over previous
#include <cuda_runtime.h>
#include <cuda_bf16.h>
#include <math.h>
#include <stdint.h>

#define B_ 4
#define N_ 1024
#define HW_ 4096
#define D_ 512
#define H_ 8
#define DK_ 64
#define ZTOT (B_ * H_)
#define DD (D_ * D_)

// ---------------- scratch (static device globals; no allocation) -----------
__device__ __nv_bfloat16 g_qh[B_ * N_ * D_],  g_ql[B_ * N_ * D_];
__device__ __nv_bfloat16 g_kh[B_ * HW_ * D_], g_kl[B_ * HW_ * D_];
__device__ __nv_bfloat16 g_vh[B_ * HW_ * D_], g_vl[B_ * HW_ * D_];
__device__ __nv_bfloat16 g_wh[4 * DD], g_wl[4 * DD];     // wq|wk|wv|wo
__device__ __nv_bfloat16 g_Qh[B_ * N_ * D_],  g_Ql[B_ * N_ * D_];
__device__ __nv_bfloat16 g_Kh[B_ * HW_ * D_], g_Kl[B_ * HW_ * D_];
__device__ __nv_bfloat16 g_Vh[B_ * HW_ * D_], g_Vl[B_ * HW_ * D_];
__device__ __nv_bfloat16 g_ctxh[B_ * N_ * D_], g_ctxl[B_ * N_ * D_];
__device__ unsigned char g_mask[N_ * HW_];

// ---------------- helpers --------------------------------------------------
__device__ __forceinline__ uint32_t smem_u32(const void* p) {
    return (uint32_t)__cvta_generic_to_shared(p);
}
__device__ __forceinline__ void cp16(uint32_t s, const void* g) {
    asm volatile("cp.async.cg.shared.global [%0],[%1],16;" :: "r"(s), "l"(g));
}
__device__ __forceinline__ void cp_commit() {
    asm volatile("cp.async.commit_group;" ::: "memory");
}
template <int NN>
__device__ __forceinline__ void cp_wait() {
    asm volatile("cp.async.wait_group %0;" :: "n"(NN) : "memory");
}
__device__ __forceinline__ void ldsm4(uint32_t& r0, uint32_t& r1, uint32_t& r2,
                                      uint32_t& r3, uint32_t a) {
    asm volatile("ldmatrix.sync.aligned.m8n8.x4.shared.b16 {%0,%1,%2,%3},[%4];"
                 : "=r"(r0), "=r"(r1), "=r"(r2), "=r"(r3) : "r"(a));
}
__device__ __forceinline__ void ldsm4t(uint32_t& r0, uint32_t& r1, uint32_t& r2,
                                       uint32_t& r3, uint32_t a) {
    asm volatile("ldmatrix.sync.aligned.m8n8.x4.trans.shared.b16 {%0,%1,%2,%3},[%4];"
                 : "=r"(r0), "=r"(r1), "=r"(r2), "=r"(r3) : "r"(a));
}
__device__ __forceinline__ void mma_bf16(float* c, const uint32_t* a, const uint32_t* b) {
    asm volatile(
        "mma.sync.aligned.m16n8k16.row.col.f32.bf16.bf16.f32 "
        "{%0,%1,%2,%3},{%4,%5,%6,%7},{%8,%9},{%0,%1,%2,%3};"
        : "+f"(c[0]), "+f"(c[1]), "+f"(c[2]), "+f"(c[3])
        : "r"(a[0]), "r"(a[1]), "r"(a[2]), "r"(a[3]), "r"(b[0]), "r"(b[1]));
}
__device__ __forceinline__ void mma2(float* c, const uint32_t* a, uint32_t b0, uint32_t b1) {
    uint32_t b[2] = {b0, b1};
    mma_bf16(c, a, b);
}
__device__ __forceinline__ void split2(float x, float y, uint32_t& hi, uint32_t& lo) {
    __nv_bfloat16 hx = __float2bfloat16(x);
    __nv_bfloat16 hy = __float2bfloat16(y);
    __nv_bfloat16 lx = __float2bfloat16(x - __bfloat162float(hx));
    __nv_bfloat16 ly = __float2bfloat16(y - __bfloat162float(hy));
    hi = (uint32_t)__bfloat16_as_ushort(hx) | ((uint32_t)__bfloat16_as_ushort(hy) << 16);
    lo = (uint32_t)__bfloat16_as_ushort(lx) | ((uint32_t)__bfloat16_as_ushort(ly) << 16);
}

// ---------------- split kernels --------------------------------------------
__global__ void split2x_kernel(const float4* __restrict__ X0, uint2* __restrict__ H0,
                               uint2* __restrict__ L0, int n0,
                               const float4* __restrict__ X1, uint2* __restrict__ H1,
                               uint2* __restrict__ L1, int n1) {
    int i = blockIdx.x * blockDim.x + threadIdx.x;
    const float4* X;
    uint2 *Hd, *Ld;
    int j;
    if (i < n0) { X = X0; Hd = H0; Ld = L0; j = i; }
    else {
        j = i - n0;
        if (j >= n1) return;
        X = X1; Hd = H1; Ld = L1;
    }
    float4 v = X[j];
    uint32_t h0, l0, h1, l1;
    split2(v.x, v.y, h0, l0);
    split2(v.z, v.w, h1, l1);
    Hd[j] = make_uint2(h0, h1);
    Ld[j] = make_uint2(l0, l1);
}

__global__ void split_kernel(const float4* __restrict__ X, uint2* __restrict__ Xh,
                             uint2* __restrict__ Xl, int n4) {
    int i = blockIdx.x * blockDim.x + threadIdx.x;
    if (i >= n4) return;
    float4 v = X[i];
    uint32_t h0, l0, h1, l1;
    split2(v.x, v.y, h0, l0);
    split2(v.z, v.w, h1, l1);
    Xh[i] = make_uint2(h0, h1);
    Xl[i] = make_uint2(l0, l1);
}

__global__ void splitw_kernel(const float4* __restrict__ W0, const float4* __restrict__ W1,
                              const float4* __restrict__ W2, const float4* __restrict__ W3,
                              uint2* __restrict__ Hd, uint2* __restrict__ Ld) {
    int i = blockIdx.x * blockDim.x + threadIdx.x;   // 0 .. 4*DD/4-1
    if (i >= DD) return;                              // DD = 4 arrays * DD/4 float4
    int a = i >> 16;                                  // DD/4 = 65536 per array
    int r = i & 0xFFFF;
    const float4* src = a == 0 ? W0 : a == 1 ? W1 : a == 2 ? W2 : W3;
    float4 v = src[r];
    uint32_t h0, l0, h1, l1;
    split2(v.x, v.y, h0, l0);
    split2(v.z, v.w, h1, l1);
    Hd[i] = make_uint2(h0, h1);
    Ld[i] = make_uint2(l0, l1);
}

// ---------------- mask precompute ------------------------------------------
__global__ void mask_kernel(const float* __restrict__ x_tilde,
                            const float* __restrict__ x_hat,
                            unsigned char* __restrict__ mask) {
    int idx = blockIdx.x * blockDim.x + threadIdx.x;
    if (idx >= N_ * HW_) return;
    int m = idx & (HW_ - 1);
    float dx = x_tilde[m * 2 + 0] - x_hat[(size_t)idx * 2 + 0];
    float dy = x_tilde[m * 2 + 1] - x_hat[(size_t)idx * 2 + 1];
    mask[idx] = (sqrtf(dx * dx + dy * dy) < 0.1f) ? 1 : 0;
}

// ---------------- shared GEMM body (128x128 tile, K=512, split-bf16) -------
// C[m0:m0+128, n0:n0+128] = A @ B^T + bias; lda=ldb=ldc=512.
#define GBM 128
#define GBN 128
#define GBK 32
#define GSA (GBK + 8)
#define GASZ (GBM * GSA)
#define GBSZ (GBN * GSA)
#define GSTRIDE (2 * GASZ + 2 * GBSZ)
#define SMEM_BIG (3 * GSTRIDE * 2)

template <bool SPLITOUT>
__device__ __forceinline__ void gemm_body(
    __nv_bfloat16* smem,
    const __nv_bfloat16* __restrict__ Agh, const __nv_bfloat16* __restrict__ Agl,
    const __nv_bfloat16* __restrict__ Bgh, const __nv_bfloat16* __restrict__ Bgl,
    const float* __restrict__ bias, float* __restrict__ C,
    __nv_bfloat16* __restrict__ Ch, __nv_bfloat16* __restrict__ Cl,
    int m0, int n0) {
    constexpr int STAGES = 3;
    constexpr int WM = 64, WN = 32;
    constexpr int WNC = GBN / WN;         // 4
    constexpr int MT = WM / 16;           // 4
    constexpr int NT = WN / 8;            // 4
    constexpr int NTP = NT / 2;           // 2

    int tid = threadIdx.x;
    int lane = tid & 31;
    int wid = tid >> 5;
    int wm0 = (wid / WNC) * WM;
    int wn0 = (wid % WNC) * WN;

    const int nK = D_ / GBK;              // 16
    uint32_t smem_b = smem_u32(smem);

    auto issue = [&](int kc) {
        int s = kc % STAGES;
        int k0 = kc * GBK;
        uint32_t base = smem_b + (uint32_t)(s * GSTRIDE) * 2;
        for (int i = tid; i < GBM * (GBK / 8); i += 256) {
            int r = i / (GBK / 8);
            int c = (i % (GBK / 8)) * 8;
            long go = (long)(m0 + r) * D_ + k0 + c;
            uint32_t so = (uint32_t)(r * GSA + c) * 2;
            cp16(base + so, Agh + go);
            cp16(base + (uint32_t)GASZ * 2 + so, Agl + go);
        }
        uint32_t bb = base + (uint32_t)(2 * GASZ) * 2;
        for (int i = tid; i < GBN * (GBK / 8); i += 256) {
            int r = i / (GBK / 8);
            int c = (i % (GBK / 8)) * 8;
            long go = (long)(n0 + r) * D_ + k0 + c;
            uint32_t so = (uint32_t)(r * GSA + c) * 2;
            cp16(bb + so, Bgh + go);
            cp16(bb + (uint32_t)GBSZ * 2 + so, Bgl + go);
        }
    };

    float acc[MT][NT][4];
#pragma unroll
    for (int i = 0; i < MT; i++)
#pragma unroll
        for (int j = 0; j < NT; j++)
#pragma unroll
            for (int q = 0; q < 4; q++) acc[i][j][q] = 0.0f;

    for (int s = 0; s < STAGES - 1; s++) {
        if (s < nK) issue(s);
        cp_commit();
    }

    for (int kc = 0; kc < nK; kc++) {
        int pf = kc + STAGES - 1;
        if (pf < nK) issue(pf);
        cp_commit();
        cp_wait<STAGES - 1>();
        __syncthreads();

        int s = kc % STAGES;
        const __nv_bfloat16* Ah_s = smem + s * GSTRIDE;
        const __nv_bfloat16* Al_s = Ah_s + GASZ;
        const __nv_bfloat16* Bh_s = Ah_s + 2 * GASZ;
        const __nv_bfloat16* Bl_s = Bh_s + GBSZ;

#pragma unroll
        for (int ks = 0; ks < GBK / 16; ks++) {
            uint32_t af[MT][4], al_[MT][4];
#pragma unroll
            for (int mt = 0; mt < MT; mt++) {
                int row = wm0 + mt * 16 + (lane & 15);
                int col = ks * 16 + (lane >> 4) * 8;
                ldsm4(af[mt][0], af[mt][1], af[mt][2], af[mt][3],
                      smem_u32(&Ah_s[row * GSA + col]));
                ldsm4(al_[mt][0], al_[mt][1], al_[mt][2], al_[mt][3],
                      smem_u32(&Al_s[row * GSA + col]));
            }
            uint32_t bfr[NT][2], blr[NT][2];
#pragma unroll
            for (int ntp = 0; ntp < NTP; ntp++) {
                int g = lane >> 3;
                int noff = (g >> 1) * 8;
                int koff = (g & 1) * 8;
                uint32_t r0, r1, r2, r3;
                int row = wn0 + ntp * 16 + noff + (lane & 7);
                int col = ks * 16 + koff;
                ldsm4(r0, r1, r2, r3, smem_u32(&Bh_s[row * GSA + col]));
                bfr[2 * ntp][0] = r0; bfr[2 * ntp][1] = r1;
                bfr[2 * ntp + 1][0] = r2; bfr[2 * ntp + 1][1] = r3;
                ldsm4(r0, r1, r2, r3, smem_u32(&Bl_s[row * GSA + col]));
                blr[2 * ntp][0] = r0; blr[2 * ntp][1] = r1;
                blr[2 * ntp + 1][0] = r2; blr[2 * ntp + 1][1] = r3;
            }
#pragma unroll
            for (int mt = 0; mt < MT; mt++)
#pragma unroll
                for (int nt = 0; nt < NT; nt++) {
                    mma_bf16(acc[mt][nt], af[mt], bfr[nt]);
                    mma_bf16(acc[mt][nt], af[mt], blr[nt]);
                    mma_bf16(acc[mt][nt], al_[mt], bfr[nt]);
                }
        }
        __syncthreads();
    }

#pragma unroll
    for (int mt = 0; mt < MT; mt++)
#pragma unroll
        for (int nt = 0; nt < NT; nt++) {
            int row = m0 + wm0 + mt * 16 + (lane >> 2);
            int col = n0 + wn0 + nt * 8 + (lane & 3) * 2;
            float bx = bias[col], by = bias[col + 1];
            float v0x = acc[mt][nt][0] + bx;
            float v0y = acc[mt][nt][1] + by;
            float v1x = acc[mt][nt][2] + bx;
            float v1y = acc[mt][nt][3] + by;
            if constexpr (SPLITOUT) {
                uint32_t hh, ll;
                split2(v0x, v0y, hh, ll);
                *(uint32_t*)&Ch[(long)row * D_ + col] = hh;
                *(uint32_t*)&Cl[(long)row * D_ + col] = ll;
                split2(v1x, v1y, hh, ll);
                *(uint32_t*)&Ch[(long)(row + 8) * D_ + col] = hh;
                *(uint32_t*)&Cl[(long)(row + 8) * D_ + col] = ll;
            } else {
                *(float2*)&C[(long)row * D_ + col] = make_float2(v0x, v0y);
                *(float2*)&C[(long)(row + 8) * D_ + col] = make_float2(v1x, v1y);
            }
        }
}

// ---------------- merged Q/K/V projection ----------------------------------
// grid (4, 288): y<32 -> Q proj, y<160 -> K proj, else V proj.
__global__ void __launch_bounds__(256) qkv_proj(
    const __nv_bfloat16* __restrict__ qh, const __nv_bfloat16* __restrict__ ql,
    const __nv_bfloat16* __restrict__ kh, const __nv_bfloat16* __restrict__ kl,
    const __nv_bfloat16* __restrict__ vh, const __nv_bfloat16* __restrict__ vl,
    const __nv_bfloat16* __restrict__ wh, const __nv_bfloat16* __restrict__ wl,
    const float* __restrict__ bq, const float* __restrict__ bk,
    const float* __restrict__ bv,
    __nv_bfloat16* __restrict__ Qh, __nv_bfloat16* __restrict__ Ql,
    __nv_bfloat16* __restrict__ Kh, __nv_bfloat16* __restrict__ Kl,
    __nv_bfloat16* __restrict__ Vh, __nv_bfloat16* __restrict__ Vl) {
    extern __shared__ __nv_bfloat16 smem[];
    int yb = blockIdx.y;
    const __nv_bfloat16 *Ah, *Al, *Bh, *Bl;
    const float* bias;
    __nv_bfloat16 *Ch, *Cl;
    int m0;
    if (yb < 32)       { Ah = qh; Al = ql; Bh = wh;          Bl = wl;          bias = bq; Ch = Qh; Cl = Ql; m0 = yb * 128; }
    else if (yb < 160) { Ah = kh; Al = kl; Bh = wh + DD;     Bl = wl + DD;     bias = bk; Ch = Kh; Cl = Kl; m0 = (yb - 32) * 128; }
    else               { Ah = vh; Al = vl; Bh = wh + 2 * DD; Bl = wl + 2 * DD; bias = bv; Ch = Vh; Cl = Vl; m0 = (yb - 160) * 128; }
    gemm_body<true>(smem, Ah, Al, Bh, Bl, bias, nullptr, Ch, Cl,
                    m0, blockIdx.x * 128);
}

// ---------------- out projection -------------------------------------------
__global__ void __launch_bounds__(256) out_proj(
    const __nv_bfloat16* __restrict__ ch, const __nv_bfloat16* __restrict__ cl,
    const __nv_bfloat16* __restrict__ wh, const __nv_bfloat16* __restrict__ wl,
    const float* __restrict__ bo, float* __restrict__ out) {
    extern __shared__ __nv_bfloat16 smem[];
    gemm_body<false>(smem, ch, cl, wh + 3 * DD, wl + 3 * DD, bo, out,
                     nullptr, nullptr, blockIdx.y * 128, blockIdx.x * 128);
}

// ---------------- fused flash-style attention -------------------------------
#define CH_ 128
#define KROW_ 72
#define KSZB_ (128 * KROW_ * 2)
#define MROW_ 144
#define MSZB_ (128 * MROW_)
#define STAGEB_ (4 * KSZB_ + MSZB_)
#define FUSED_SMEM (2 * STAGEB_)

__global__ void __launch_bounds__(256) fused_attn(
    const __nv_bfloat16* __restrict__ Qh, const __nv_bfloat16* __restrict__ Ql,
    const __nv_bfloat16* __restrict__ Kh, const __nv_bfloat16* __restrict__ Kl,
    const __nv_bfloat16* __restrict__ Vh, const __nv_bfloat16* __restrict__ Vl,
    const unsigned char* __restrict__ mask, float* __restrict__ attn,
    __nv_bfloat16* __restrict__ Ch, __nv_bfloat16* __restrict__ Cl) {
    extern __shared__ char smc[];
    uint32_t sb = smem_u32(smc);

    int z = blockIdx.y;
    int b = z >> 3, h = z & 7;
    int q0 = blockIdx.x * 128;
    int tid = threadIdx.x;
    int lane = tid & 31;
    int w = tid >> 5;
    int lr = lane >> 2;
    int lq = lane & 3;

    const __nv_bfloat16* Qbh = Qh + ((long)(b * N_ + q0)) * D_ + h * DK_;
    const __nv_bfloat16* Qbl = Ql + ((long)(b * N_ + q0)) * D_ + h * DK_;
    const __nv_bfloat16* Kbh = Kh + (long)b * HW_ * D_ + h * DK_;
    const __nv_bfloat16* Kbl = Kl + (long)b * HW_ * D_ + h * DK_;
    const __nv_bfloat16* Vbh = Vh + (long)b * HW_ * D_ + h * DK_;
    const __nv_bfloat16* Vbl = Vl + (long)b * HW_ * D_ + h * DK_;
    const unsigned char* mrow = mask + (long)q0 * HW_;
    float* attn_z = attn + ((long)z * N_ + q0) * HW_;

    // stage Q, load fragments
    for (int i = tid; i < 1024; i += 256) {
        int r = i >> 3;
        int c = (i & 7) * 8;
        cp16(sb + (uint32_t)(r * KROW_ + c) * 2, Qbh + (long)r * D_ + c);
        cp16(sb + KSZB_ + (uint32_t)(r * KROW_ + c) * 2, Qbl + (long)r * D_ + c);
    }
    cp_commit();
    cp_wait<0>();
    __syncthreads();

    uint32_t qfh[4][4], qfl[4][4];
#pragma unroll
    for (int ks = 0; ks < 4; ks++) {
        int row = w * 16 + (lane & 15);
        int col = ks * 16 + (lane >> 4) * 8;
        ldsm4(qfh[ks][0], qfh[ks][1], qfh[ks][2], qfh[ks][3],
              sb + (uint32_t)(row * KROW_ + col) * 2);
        ldsm4(qfl[ks][0], qfl[ks][1], qfl[ks][2], qfl[ks][3],
              sb + KSZB_ + (uint32_t)(row * KROW_ + col) * 2);
    }
    __syncthreads();

    auto issue_kv = [&](int kc, bool with_v) {
        uint32_t base = sb + (uint32_t)((kc & 1) * STAGEB_);
        int mc = kc * CH_;
        for (int i = tid; i < 1024; i += 256) {
            int r = i >> 3;
            int c = (i & 7) * 8;
            long go = (long)(mc + r) * D_ + c;
            uint32_t so = (uint32_t)(r * KROW_ + c) * 2;
            cp16(base + so, Kbh + go);
            cp16(base + KSZB_ + so, Kbl + go);
            if (with_v) {
                cp16(base + 2 * KSZB_ + so, Vbh + go);
                cp16(base + 3 * KSZB_ + so, Vbl + go);
            }
        }
        for (int i = tid; i < 1024; i += 256) {
            int r = i >> 3;
            int c = (i & 7) * 16;
            cp16(base + 4 * KSZB_ + (uint32_t)(r * MROW_ + c),
                 mrow + (long)r * HW_ + mc + c);
        }
    };

    float ctx[8][4];
#pragma unroll
    for (int j = 0; j < 8; j++)
#pragma unroll
        for (int q = 0; q < 4; q++) ctx[j][q] = 0.0f;
    float rs0 = 0.0f, rs1 = 0.0f;
    float sacc[16][4];

    // ========== PASS 1 ==========
    issue_kv(0, true);
    cp_commit();
    for (int kc = 0; kc < HW_ / CH_; kc++) {
        if (kc + 1 < HW_ / CH_) {
            issue_kv(kc + 1, true);
            cp_commit();
            cp_wait<1>();
        } else {
            cp_wait<0>();
        }
        __syncthreads();

        uint32_t base = sb + (uint32_t)((kc & 1) * STAGEB_);
        uint32_t kh_b = base, kl_b = base + KSZB_;
        uint32_t vh_b = base + 2 * KSZB_, vl_b = base + 3 * KSZB_;
        uint32_t mk_b = base + 4 * KSZB_;

#pragma unroll
        for (int nt = 0; nt < 16; nt++)
#pragma unroll
            for (int q = 0; q < 4; q++) sacc[nt][q] = 0.0f;

#pragma unroll
        for (int ks = 0; ks < 4; ks++) {
#pragma unroll
            for (int ntp = 0; ntp < 8; ntp++) {
                int g = lane >> 3;
                int row = ntp * 16 + (g >> 1) * 8 + (lane & 7);
                int col = ks * 16 + (g & 1) * 8;
                uint32_t h0, h1, h2, h3, l0, l1, l2, l3;
                ldsm4(h0, h1, h2, h3, kh_b + (uint32_t)(row * KROW_ + col) * 2);
                ldsm4(l0, l1, l2, l3, kl_b + (uint32_t)(row * KROW_ + col) * 2);
                mma2(sacc[2 * ntp], qfh[ks], h0, h1);
                mma2(sacc[2 * ntp], qfh[ks], l0, l1);
                mma2(sacc[2 * ntp], qfl[ks], h0, h1);
                mma2(sacc[2 * ntp + 1], qfh[ks], h2, h3);
                mma2(sacc[2 * ntp + 1], qfh[ks], l2, l3);
                mma2(sacc[2 * ntp + 1], qfl[ks], h2, h3);
            }
        }

#pragma unroll
        for (int nt = 0; nt < 16; nt++) {
            uint32_t mo = (uint32_t)((w * 16 + lr) * MROW_ + nt * 8 + lq * 2);
            unsigned short m0 = *(unsigned short*)(smc + (mk_b - sb) + mo);
            unsigned short m1 = *(unsigned short*)(smc + (mk_b - sb) + mo + 8 * MROW_);
            float e0 = (m0 & 0xFF) ? __expf(sacc[nt][0] * 0.125f) : 0.0f;
            float e1 = (m0 >> 8)   ? __expf(sacc[nt][1] * 0.125f) : 0.0f;
            float e2 = (m1 & 0xFF) ? __expf(sacc[nt][2] * 0.125f) : 0.0f;
            float e3 = (m1 >> 8)   ? __expf(sacc[nt][3] * 0.125f) : 0.0f;
            rs0 += e0 + e1;
            rs1 += e2 + e3;
            sacc[nt][0] = e0; sacc[nt][1] = e1;
            sacc[nt][2] = e2; sacc[nt][3] = e3;
        }

#pragma unroll
        for (int kt = 0; kt < 8; kt++) {
            uint32_t ah[4], al_[4];
            split2(sacc[2 * kt][0], sacc[2 * kt][1], ah[0], al_[0]);
            split2(sacc[2 * kt][2], sacc[2 * kt][3], ah[1], al_[1]);
            split2(sacc[2 * kt + 1][0], sacc[2 * kt + 1][1], ah[2], al_[2]);
            split2(sacc[2 * kt + 1][2], sacc[2 * kt + 1][3], ah[3], al_[3]);
#pragma unroll
            for (int ntp = 0; ntp < 4; ntp++) {
                int g = lane >> 3;
                int row = kt * 16 + (g & 1) * 8 + (lane & 7);
                int col = ntp * 16 + (g >> 1) * 8;
                uint32_t h0, h1, h2, h3, l0, l1, l2, l3;
                ldsm4t(h0, h1, h2, h3, vh_b + (uint32_t)(row * KROW_ + col) * 2);
                ldsm4t(l0, l1, l2, l3, vl_b + (uint32_t)(row * KROW_ + col) * 2);
                mma2(ctx[2 * ntp], ah, h0, h1);
                mma2(ctx[2 * ntp], ah, l0, l1);
                mma2(ctx[2 * ntp], al_, h0, h1);
                mma2(ctx[2 * ntp + 1], ah, h2, h3);
                mma2(ctx[2 * ntp + 1], ah, l2, l3);
                mma2(ctx[2 * ntp + 1], al_, h2, h3);
            }
        }
        __syncthreads();
    }

    rs0 += __shfl_xor_sync(0xffffffffu, rs0, 1);
    rs0 += __shfl_xor_sync(0xffffffffu, rs0, 2);
    rs1 += __shfl_xor_sync(0xffffffffu, rs1, 1);
    rs1 += __shfl_xor_sync(0xffffffffu, rs1, 2);
    float inv0 = 1.0f / rs0;
    float inv1 = 1.0f / rs1;

#pragma unroll
    for (int nt = 0; nt < 8; nt++) {
        int row = w * 16 + lr;
        int col = nt * 8 + lq * 2;
        long off = ((long)(b * N_ + q0 + row)) * D_ + h * DK_ + col;
        uint32_t hh, ll;
        split2(ctx[nt][0] * inv0, ctx[nt][1] * inv0, hh, ll);
        *(uint32_t*)&Ch[off] = hh;
        *(uint32_t*)&Cl[off] = ll;
        split2(ctx[nt][2] * inv1, ctx[nt][3] * inv1, hh, ll);
        *(uint32_t*)&Ch[off + 8 * D_] = hh;
        *(uint32_t*)&Cl[off + 8 * D_] = ll;
    }

    // ========== PASS 2 ==========
    issue_kv(0, false);
    cp_commit();
    for (int kc = 0; kc < HW_ / CH_; kc++) {
        if (kc + 1 < HW_ / CH_) {
            issue_kv(kc + 1, false);
            cp_commit();
            cp_wait<1>();
        } else {
            cp_wait<0>();
        }
        __syncthreads();

        uint32_t base = sb + (uint32_t)((kc & 1) * STAGEB_);
        uint32_t kh_b = base, kl_b = base + KSZB_;
        uint32_t mk_b = base + 4 * KSZB_;
        int mc = kc * CH_;

#pragma unroll
        for (int nt = 0; nt < 16; nt++)
#pragma unroll
            for (int q = 0; q < 4; q++) sacc[nt][q] = 0.0f;

#pragma unroll
        for (int ks = 0; ks < 4; ks++) {
#pragma unroll
            for (int ntp = 0; ntp < 8; ntp++) {
                int g = lane >> 3;
                int row = ntp * 16 + (g >> 1) * 8 + (lane & 7);
                int col = ks * 16 + (g & 1) * 8;
                uint32_t h0, h1, h2, h3, l0, l1, l2, l3;
                ldsm4(h0, h1, h2, h3, kh_b + (uint32_t)(row * KROW_ + col) * 2);
                ldsm4(l0, l1, l2, l3, kl_b + (uint32_t)(row * KROW_ + col) * 2);
                mma2(sacc[2 * ntp], qfh[ks], h0, h1);
                mma2(sacc[2 * ntp], qfh[ks], l0, l1);
                mma2(sacc[2 * ntp], qfl[ks], h0, h1);
                mma2(sacc[2 * ntp + 1], qfh[ks], h2, h3);
                mma2(sacc[2 * ntp + 1], qfh[ks], l2, l3);
                mma2(sacc[2 * ntp + 1], qfl[ks], h2, h3);
            }
        }

        int grow0 = w * 16 + lr;
#pragma unroll
        for (int nt = 0; nt < 16; nt++) {
            uint32_t mo = (uint32_t)(grow0 * MROW_ + nt * 8 + lq * 2);
            unsigned short m0 = *(unsigned short*)(smc + (mk_b - sb) + mo);
            unsigned short m1 = *(unsigned short*)(smc + (mk_b - sb) + mo + 8 * MROW_);
            float e0 = (m0 & 0xFF) ? __expf(sacc[nt][0] * 0.125f) * inv0 : 0.0f;
            float e1 = (m0 >> 8)   ? __expf(sacc[nt][1] * 0.125f) * inv0 : 0.0f;
            float e2 = (m1 & 0xFF) ? __expf(sacc[nt][2] * 0.125f) * inv1 : 0.0f;
            float e3 = (m1 >> 8)   ? __expf(sacc[nt][3] * 0.125f) * inv1 : 0.0f;
            int col = mc + nt * 8 + lq * 2;
            *(float2*)(attn_z + (long)grow0 * HW_ + col) = make_float2(e0, e1);
            *(float2*)(attn_z + (long)(grow0 + 8) * HW_ + col) = make_float2(e2, e3);
        }
        __syncthreads();
    }
}

// ---------------- launch ---------------------------------------------------
extern "C" void kernel_launch(void* const* d_in, const int* in_sizes, int n_in,
                              void* d_out, int out_size) {
    const float* query   = (const float*)d_in[0];
    const float* key     = (const float*)d_in[1];
    const float* value   = (const float*)d_in[2];
    const float* x_tilde = (const float*)d_in[3];
    const float* x_hat   = (const float*)d_in[4];
    const float* Wq = (const float*)d_in[5];
    const float* bq = (const float*)d_in[6];
    const float* Wk = (const float*)d_in[7];
    const float* bk = (const float*)d_in[8];
    const float* Wv = (const float*)d_in[9];
    const float* bv = (const float*)d_in[10];
    const float* Wo = (const float*)d_in[11];
    const float* bo = (const float*)d_in[12];

    float* out = (float*)d_out;
    float* attn = out + (size_t)B_ * N_ * D_;

    __nv_bfloat16 *qh, *ql, *kh, *kl, *vh, *vl, *wh, *wl;
    __nv_bfloat16 *Qh, *Ql, *Kh, *Kl, *Vh, *Vl, *ch, *cl;
    unsigned char* Mp;
    cudaGetSymbolAddress((void**)&qh, g_qh);   cudaGetSymbolAddress((void**)&ql, g_ql);
    cudaGetSymbolAddress((void**)&kh, g_kh);   cudaGetSymbolAddress((void**)&kl, g_kl);
    cudaGetSymbolAddress((void**)&vh, g_vh);   cudaGetSymbolAddress((void**)&vl, g_vl);
    cudaGetSymbolAddress((void**)&wh, g_wh);   cudaGetSymbolAddress((void**)&wl, g_wl);
    cudaGetSymbolAddress((void**)&Qh, g_Qh);   cudaGetSymbolAddress((void**)&Ql, g_Ql);
    cudaGetSymbolAddress((void**)&Kh, g_Kh);   cudaGetSymbolAddress((void**)&Kl, g_Kl);
    cudaGetSymbolAddress((void**)&Vh, g_Vh);   cudaGetSymbolAddress((void**)&Vl, g_Vl);
    cudaGetSymbolAddress((void**)&ch, g_ctxh); cudaGetSymbolAddress((void**)&cl, g_ctxl);
    cudaGetSymbolAddress((void**)&Mp, g_mask);

    cudaFuncSetAttribute(qkv_proj, cudaFuncAttributeMaxDynamicSharedMemorySize, SMEM_BIG);
    cudaFuncSetAttribute(out_proj, cudaFuncAttributeMaxDynamicSharedMemorySize, SMEM_BIG);
    cudaFuncSetAttribute(fused_attn, cudaFuncAttributeMaxDynamicSharedMemorySize,
                         FUSED_SMEM);

    // launch 0: mask
    mask_kernel<<<(N_ * HW_ + 255) / 256, 256>>>(x_tilde, x_hat, Mp);

    // launch 1: split query + key
    {
        int nq = B_ * N_ * D_ / 4, nk = B_ * HW_ * D_ / 4;
        split2x_kernel<<<(nq + nk + 255) / 256, 256>>>(
            (const float4*)query, (uint2*)qh, (uint2*)ql, nq,
            (const float4*)key, (uint2*)kh, (uint2*)kl, nk);
    }
    // launch 2: split value
    split_kernel<<<(B_ * HW_ * D_ / 4 + 255) / 256, 256>>>(
        (const float4*)value, (uint2*)vh, (uint2*)vl, B_ * HW_ * D_ / 4);
    // launch 3: split weights (wq|wk|wv|wo into contiguous buffer)
    splitw_kernel<<<(DD + 255) / 256, 256>>>(
        (const float4*)Wq, (const float4*)Wk, (const float4*)Wv, (const float4*)Wo,
        (uint2*)wh, (uint2*)wl);

    // launch 4: merged Q/K/V projections
    qkv_proj<<<dim3(4, 288), 256, SMEM_BIG>>>(qh, ql, kh, kl, vh, vl, wh, wl,
                                              bq, bk, bv, Qh, Ql, Kh, Kl, Vh, Vl);

    // launch 5: fused attention (ncu -s 5 captures this)
    fused_attn<<<dim3(N_ / 128, ZTOT), 256, FUSED_SMEM>>>(
        Qh, Ql, Kh, Kl, Vh, Vl, Mp, attn, ch, cl);

    // launch 6: out projection
    out_proj<<<dim3(4, 32), 256, SMEM_BIG>>>(ch, cl, wh, wl, bo, out);
}